// round 4
// baseline (speedup 1.0000x reference)
#include <cuda_runtime.h>
#include <cuda_fp16.h>
#include <cstdint>

#define NUM_LEVELS 16
#define LOG2_HASHMAP 19
#define TABLE_SIZE (1u << LOG2_HASHMAP)
#define HASH_MASK (TABLE_SIZE - 1u)
#define N_QUERIES (1 << 20)

#define P1 2654435761u
#define P2 805459861u

// Dense cell tables for coarse levels 0..2 (side = res+1 cells per dim)
#define N0 4913      // 17^3
#define N1 35937     // 33^3
#define N2 274625    // 65^3
#define NCELLS (N0 + N1 + N2)
#define OFF0 0
#define OFF1 (N0 * 2)
#define OFF2 ((N0 + N1) * 2)
#define CELL_U4 (NCELLS * 2)

// fp16-repacked hash table: entry i of level l at g_tab[l*TABLE_SIZE + i]
__device__ uint32_t g_tab[NUM_LEVELS * TABLE_SIZE];
// per-cell 8-corner table for levels 0..2: 2 uint4 (32B) per cell
__device__ uint4 g_cell[CELL_U4];

__global__ void __launch_bounds__(256)
convert_kernel(const float4* __restrict__ emb)
{
    int i = blockIdx.x * blockDim.x + threadIdx.x;   // 2 entries per thread
    float4 e = emb[i];
    __half2 a = __floats2half2_rn(e.x, e.y);
    __half2 b = __floats2half2_rn(e.z, e.w);
    uint2 pk;
    pk.x = *reinterpret_cast<uint32_t*>(&a);
    pk.y = *reinterpret_cast<uint32_t*>(&b);
    reinterpret_cast<uint2*>(g_tab)[i] = pk;
}

__global__ void __launch_bounds__(256)
cell_kernel()
{
    int i = blockIdx.x * blockDim.x + threadIdx.x;
    if (i >= NCELLS) return;
    int l, side, loc, off;
    if (i < N0)           { l = 0; side = 17; loc = i;            off = OFF0; }
    else if (i < N0 + N1) { l = 1; side = 33; loc = i - N0;       off = OFF1; }
    else                  { l = 2; side = 65; loc = i - N0 - N1;  off = OFF2; }
    int c2 = loc % side;
    int r  = loc / side;
    int c1 = r % side;
    int c0 = r / side;
    c0 -= 1; c1 -= 1; c2 -= 1;     // cell coords range [-1, res-1]

    const uint32_t* tab = g_tab + (size_t)l * TABLE_SIZE;
    uint32_t v[8];
#pragma unroll
    for (int o = 0; o < 8; o++) {
        uint32_t a = (uint32_t)(c0 + (o >> 2));
        uint32_t b = (uint32_t)(c1 + ((o >> 1) & 1));
        uint32_t c = (uint32_t)(c2 + (o & 1));
        uint32_t h = (a ^ (b * P1) ^ (c * P2)) & HASH_MASK;
        v[o] = tab[h];
    }
    g_cell[off + loc * 2]     = make_uint4(v[0], v[1], v[2], v[3]);
    g_cell[off + loc * 2 + 1] = make_uint4(v[4], v[5], v[6], v[7]);
}

__device__ __forceinline__ float2 h2f(uint32_t u)
{
    __half2 h = *reinterpret_cast<__half2*>(&u);
    return __half22float2(h);
}

__device__ __forceinline__ uint32_t sel4(uint4 q, uint32_t s)
{
    uint32_t lo = (s & 1) ? q.y : q.x;
    uint32_t hi = (s & 1) ? q.w : q.z;
    return (s & 2) ? hi : lo;
}

__global__ void __launch_bounds__(256)
grid_encode_kernel(const float* __restrict__ inp,
                   const int* __restrict__ bound_ptr,
                   float* __restrict__ out)
{
    int tid = blockIdx.x * blockDim.x + threadIdx.x;
    if (tid >= N_QUERIES * NUM_LEVELS) return;
    int q = tid >> 4;
    int l = tid & 15;

    float inv_b = 1.0f / (float)(*bound_ptr);

    // channel permutation [2, 0, 1]
    float x0 = inp[3 * q + 2];
    float x1 = inp[3 * q + 0];
    float x2 = inp[3 * q + 1];

    float u0 = (x0 * inv_b + 1.0f) * 0.5f;
    float u1 = (x1 * inv_b + 1.0f) * 0.5f;
    float u2 = (x2 * inv_b + 1.0f) * 0.5f;

    float res = (float)(16u << l);

    float p0 = u0 * res - 0.5f;
    float p1 = u1 * res - 0.5f;
    float p2 = u2 * res - 0.5f;

    float f0 = floorf(p0), f1 = floorf(p1), f2 = floorf(p2);
    float fr0 = p0 - f0, fr1 = p1 - f1, fr2 = p2 - f2;

    int c0 = (int)f0, c1 = (int)f1, c2 = (int)f2;

    float w0a = 1.0f - fr0, w0b = fr0;
    float w1a = 1.0f - fr1, w1b = fr1;
    float w2a = 1.0f - fr2, w2b = fr2;

    // combo weights over (dim1, dim2): index bit1 = dim1 offset, bit0 = dim2 offset
    float wc0 = w1a * w2a;
    float wc1 = w1a * w2b;
    float wc2 = w1b * w2a;
    float wc3 = w1b * w2b;

    float ox = 0.0f, oy = 0.0f;

    if (l < 3) {
        // ── dense cell path: all 8 corners in one 32B entry (1 cache line) ──
        int side = (16 << l) + 1;
        int off = (l == 0) ? OFF0 : (l == 1) ? OFF1 : OFF2;
        int cell = ((c0 + 1) * side + (c1 + 1)) * side + (c2 + 1);
        const uint4* bp = g_cell + off + (size_t)cell * 2;
        uint4 A = __ldg(bp);       // corners dim0=c0,   order (j,k) = 00,01,10,11
        uint4 B = __ldg(bp + 1);   // corners dim0=c0+1

        float2 f;
        f = h2f(A.x); ox = fmaf(w0a * wc0, f.x, ox); oy = fmaf(w0a * wc0, f.y, oy);
        f = h2f(A.y); ox = fmaf(w0a * wc1, f.x, ox); oy = fmaf(w0a * wc1, f.y, oy);
        f = h2f(A.z); ox = fmaf(w0a * wc2, f.x, ox); oy = fmaf(w0a * wc2, f.y, oy);
        f = h2f(A.w); ox = fmaf(w0a * wc3, f.x, ox); oy = fmaf(w0a * wc3, f.y, oy);
        f = h2f(B.x); ox = fmaf(w0b * wc0, f.x, ox); oy = fmaf(w0b * wc0, f.y, oy);
        f = h2f(B.y); ox = fmaf(w0b * wc1, f.x, ox); oy = fmaf(w0b * wc1, f.y, oy);
        f = h2f(B.z); ox = fmaf(w0b * wc2, f.x, ox); oy = fmaf(w0b * wc2, f.y, oy);
        f = h2f(B.w); ox = fmaf(w0b * wc3, f.x, ox); oy = fmaf(w0b * wc3, f.y, oy);
    } else {
        // ── hash path with uniform quad loads ──
        uint32_t hc0  = (uint32_t)c0;
        uint32_t hc0b = (uint32_t)(c0 + 1);
        uint32_t delta = hc0 ^ hc0b;            // 1,3,7,15,... by parity of c0
        uint32_t h1a = (uint32_t)c1 * P1;
        uint32_t h1b = (uint32_t)(c1 + 1) * P1;
        uint32_t h2a = (uint32_t)c2 * P2;
        uint32_t h2b = (uint32_t)(c2 + 1) * P2;

        uint32_t hjk0 = h1a ^ h2a;
        uint32_t hjk1 = h1a ^ h2b;
        uint32_t hjk2 = h1b ^ h2a;
        uint32_t hjk3 = h1b ^ h2b;

        uint32_t z0 = (hjk0 ^ hc0) & HASH_MASK;
        uint32_t z1 = (hjk1 ^ hc0) & HASH_MASK;
        uint32_t z2 = (hjk2 ^ hc0) & HASH_MASK;
        uint32_t z3 = (hjk3 ^ hc0) & HASH_MASK;

        const uint32_t* tab = g_tab + (size_t)l * TABLE_SIZE;

        // one 16B quad per combo always covers corner z; covers partner too if delta<4
        uint4 Q0 = __ldg((const uint4*)(tab + (z0 & ~3u)));
        uint4 Q1 = __ldg((const uint4*)(tab + (z1 & ~3u)));
        uint4 Q2 = __ldg((const uint4*)(tab + (z2 & ~3u)));
        uint4 Q3 = __ldg((const uint4*)(tab + (z3 & ~3u)));

        uint32_t e0_0 = sel4(Q0, z0 & 3u);
        uint32_t e0_1 = sel4(Q1, z1 & 3u);
        uint32_t e0_2 = sel4(Q2, z2 & 3u);
        uint32_t e0_3 = sel4(Q3, z3 & 3u);

        uint32_t e1_0, e1_1, e1_2, e1_3;
        if (delta < 4u) {
            e1_0 = sel4(Q0, (z0 & 3u) ^ delta);
            e1_1 = sel4(Q1, (z1 & 3u) ^ delta);
            e1_2 = sel4(Q2, (z2 & 3u) ^ delta);
            e1_3 = sel4(Q3, (z3 & 3u) ^ delta);
        } else {
            e1_0 = __ldg(tab + ((hjk0 ^ hc0b) & HASH_MASK));
            e1_1 = __ldg(tab + ((hjk1 ^ hc0b) & HASH_MASK));
            e1_2 = __ldg(tab + ((hjk2 ^ hc0b) & HASH_MASK));
            e1_3 = __ldg(tab + ((hjk3 ^ hc0b) & HASH_MASK));
        }

#define ACC(U0, U1, WC)                                            \
        {                                                          \
            float2 ea_ = h2f(U0);                                  \
            float2 eb_ = h2f(U1);                                  \
            ox = fmaf(WC, fmaf(w0a, ea_.x, w0b * eb_.x), ox);      \
            oy = fmaf(WC, fmaf(w0a, ea_.y, w0b * eb_.y), oy);      \
        }
        ACC(e0_0, e1_0, wc0);
        ACC(e0_1, e1_1, wc1);
        ACC(e0_2, e1_2, wc2);
        ACC(e0_3, e1_3, wc3);
#undef ACC
    }

    float2* o = (float2*)(out + (size_t)q * (NUM_LEVELS * 2)) + l;
    *o = make_float2(ox, oy);
}

extern "C" void kernel_launch(void* const* d_in, const int* in_sizes, int n_in,
                              void* d_out, int out_size)
{
    const float* inp   = (const float*)d_in[0];
    const float* emb   = (const float*)d_in[1];
    const int*   bound = (const int*)d_in[2];
    float* out = (float*)d_out;

    // Prepass 1: repack fp32 table -> fp16
    int conv_threads = (NUM_LEVELS * TABLE_SIZE) / 2;   // 4M threads
    convert_kernel<<<conv_threads / 256, 256>>>((const float4*)emb);

    // Prepass 2: build dense 8-corner cell tables for levels 0..2
    cell_kernel<<<(NCELLS + 255) / 256, 256>>>();

    int total = N_QUERIES * NUM_LEVELS;
    grid_encode_kernel<<<(total + 255) / 256, 256>>>(inp, bound, out);
}